// round 6
// baseline (speedup 1.0000x reference)
#include <cuda_runtime.h>
#include <cstdint>

// ---------------- problem dims ----------------
#define TT   512
#define BB   64
#define DIN  512
#define HH   1024
#define G3   3072
#define DOUT 512
#define TBR  (TT*BB)     // 32768 rows

#define NCTA 128         // persistent kernel grid
#define JSL  8           // hidden columns per CTA (128*8 = 1024)

// ---------------- device scratch (no allocations allowed) ----------------
__device__ float g_xg[(size_t)TBR * G3];   // gate pre-activations (reused as LN output)
__device__ float g_y [(size_t)TBR * HH];   // layer output sequence
__device__ float g_h [2 * BB * HH];        // ping-pong hidden state
__device__ unsigned g_flag[8 * 32];        // per-chunk producer counters (128B padded)

// ---------------- helpers ----------------
__device__ __forceinline__ unsigned f2tf(float x) {
    unsigned r;
    asm("cvt.rna.tf32.f32 %0, %1;" : "=r"(r) : "f"(x));
    return r;
}

__device__ __forceinline__ void mma8(float* c, const unsigned* a, const unsigned* b) {
    asm volatile(
        "mma.sync.aligned.m16n8k8.row.col.f32.tf32.tf32.f32 "
        "{%0,%1,%2,%3},{%4,%5,%6,%7},{%8,%9},{%0,%1,%2,%3};"
        : "+f"(c[0]), "+f"(c[1]), "+f"(c[2]), "+f"(c[3])
        : "r"(a[0]), "r"(a[1]), "r"(a[2]), "r"(a[3]), "r"(b[0]), "r"(b[1]));
}

__device__ __forceinline__ float sigmoidf_fast(float x) {
    return 1.0f / (1.0f + __expf(-x));
}

__device__ __forceinline__ void spin_acq(const unsigned* p, unsigned tgt) {
    unsigned v;
    do {
        asm volatile("ld.acquire.gpu.global.u32 %0, [%1];" : "=r"(v) : "l"(p));
    } while (v < tgt);
}

// =====================================================================
// Generic GEMM: C[M,N] = A[M,K] * B[N,K]^T + bias[N]   (tf32 tensor cores)
// CTA tile 128x128, BK=32, 256 threads, warp grid 2x4 (warp tile 64x32).
// 3-stage cp.async pipeline, one __syncthreads per BK tile, consumer-side
// tf32 conversion. Requires M,N%128==0, K%32==0 (and K>=96).
// =====================================================================
#define GST 40           // smem row stride in floats

__global__ __launch_bounds__(256, 1)
void gemm_tn(const float* __restrict__ A, const float* __restrict__ B,
             const float* __restrict__ bias, float* __restrict__ C,
             int M, int N, int K)
{
    extern __shared__ float gsm[];
    float* As = gsm;                         // [3][128][GST]
    float* Bs = gsm + 3 * 128 * GST;         // [3][128][GST]

    const int tid  = threadIdx.x;
    const int lane = tid & 31;
    const int warp = tid >> 5;
    const int wm   = (warp >> 2) * 64;   // warp grid 2 (M) x 4 (N)
    const int wn   = (warp & 3) * 32;
    const int gq   = lane >> 2;
    const int t4   = lane & 3;

    const int m0 = blockIdx.y * 128;
    const int n0 = blockIdx.x * 128;

    const int ld_row = tid >> 3;          // 0..31 (x4 iterations covers 128 rows)
    const int ld_c4  = (tid & 7) * 4;

    const int nk = K / 32;

    auto issue = [&](int slot, int i) {
        const int kt = i * 32;
#pragma unroll
        for (int r = 0; r < 4; ++r) {
            int row = ld_row + 32 * r;
            const float* srcA = &A[(size_t)(m0 + row) * K + kt + ld_c4];
            const float* srcB = &B[(size_t)(n0 + row) * K + kt + ld_c4];
            unsigned dA = (unsigned)__cvta_generic_to_shared(
                &As[(slot * 128 + row) * GST + ld_c4]);
            unsigned dB = (unsigned)__cvta_generic_to_shared(
                &Bs[(slot * 128 + row) * GST + ld_c4]);
            asm volatile("cp.async.cg.shared.global [%0], [%1], 16;" :: "r"(dA), "l"(srcA));
            asm volatile("cp.async.cg.shared.global [%0], [%1], 16;" :: "r"(dB), "l"(srcB));
        }
        asm volatile("cp.async.commit_group;" ::: "memory");
    };

    float c[4][4][4];
#pragma unroll
    for (int i = 0; i < 4; ++i)
#pragma unroll
        for (int j = 0; j < 4; ++j)
#pragma unroll
            for (int r = 0; r < 4; ++r) c[i][j][r] = 0.0f;

    issue(0, 0);
    issue(1, 1);

    for (int i = 0; i < nk; ++i) {
        if (i + 1 < nk) asm volatile("cp.async.wait_group 1;" ::: "memory");
        else            asm volatile("cp.async.wait_group 0;" ::: "memory");
        __syncthreads();                      // tile i visible; slot (i+2)%3 free
        if (i + 2 < nk) issue((i + 2) % 3, i + 2);

        const float* as = As + (i % 3) * 128 * GST;
        const float* bs = Bs + (i % 3) * 128 * GST;
#pragma unroll
        for (int kk = 0; kk < 4; ++kk) {
            const int cc = kk * 8 + 2 * t4;
            unsigned a[4][4], b[4][2];
#pragma unroll
            for (int mi = 0; mi < 4; ++mi) {
                int r0 = wm + mi * 16 + gq;
                float2 x0 = *(const float2*)&as[r0 * GST + cc];
                float2 x1 = *(const float2*)&as[(r0 + 8) * GST + cc];
                a[mi][0] = f2tf(x0.x); a[mi][1] = f2tf(x1.x);
                a[mi][2] = f2tf(x0.y); a[mi][3] = f2tf(x1.y);
            }
#pragma unroll
            for (int ni = 0; ni < 4; ++ni) {
                float2 z = *(const float2*)&bs[(wn + ni * 8 + gq) * GST + cc];
                b[ni][0] = f2tf(z.x); b[ni][1] = f2tf(z.y);
            }
#pragma unroll
            for (int mi = 0; mi < 4; ++mi)
#pragma unroll
                for (int ni = 0; ni < 4; ++ni)
                    mma8(c[mi][ni], a[mi], b[ni]);
        }
    }

    // epilogue: C = acc + bias
#pragma unroll
    for (int mi = 0; mi < 4; ++mi) {
#pragma unroll
        for (int ni = 0; ni < 4; ++ni) {
            int row = m0 + wm + mi * 16 + gq;
            int col = n0 + wn + ni * 8 + 2 * t4;
            float b0 = bias[col], b1 = bias[col + 1];
            float2 v0 = make_float2(c[mi][ni][0] + b0, c[mi][ni][1] + b1);
            float2 v1 = make_float2(c[mi][ni][2] + b0, c[mi][ni][3] + b1);
            *(float2*)&C[(size_t)row * N + col]       = v0;
            *(float2*)&C[(size_t)(row + 8) * N + col] = v1;
        }
    }
}

// =====================================================================
// Persistent GRU layer kernel.
// grid = NCTA (128), 256 threads (8 warps). CTA b owns hidden cols
// [b*8, b*8+8). Weight slice (24 x 1024) smem-resident as tf32.
// Per step: h streamed via 3-slot cp.async ring of k=128 chunks.
// Global barrier replaced by 8 per-chunk producer flags: chunk c's
// columns are produced by CTAs 16c..16c+15; each posts flag[c] after
// its epilogue; consumers acquire-poll flag[c] (target 16*t) right
// before issuing chunk c, overlapping the wait with compute.
// =====================================================================
#define WSTRIDE 1032
#define ACH     136      // A chunk row stride (128 + 8)

__global__ __launch_bounds__(256, 1)
void gru_layer(const float* __restrict__ w_hh, const float* __restrict__ b_hh)
{
    extern __shared__ char smraw[];
    unsigned* Bs  = (unsigned*)smraw;                         // [24][WSTRIDE]
    float*    As  = (float*)(smraw + 24 * WSTRIDE * 4);       // [3][64][ACH]
    float*    red = As + 3 * 64 * ACH;                        // [4*32*12]

    const int tid   = threadIdx.x;
    const int lane  = tid & 31;
    const int warp  = tid >> 5;
    const int gq    = lane >> 2;
    const int t4    = lane & 3;
    const int mt    = warp & 3;          // M-tile id
    const int khalf = warp >> 2;         // K-half within each 128-chunk
    const int r0    = mt * 16;
    const int j0    = blockIdx.x * JSL;
    const int jc    = j0 + 2 * t4;
    const int cj    = j0 >> 7;           // chunk containing this CTA's columns

    // ---- preload weight slice (24 x 1024) as tf32 ----
    for (int e = tid; e < 24 * 256; e += 256) {
        int row = e >> 8;
        int c4  = (e & 255) * 4;
        int gate = row >> 3, jj = row & 7;
        float4 v = *(const float4*)&w_hh[(size_t)(gate * HH + j0 + jj) * HH + c4];
        uint4 u; u.x = f2tf(v.x); u.y = f2tf(v.y); u.z = f2tf(v.z); u.w = f2tf(v.w);
        *(uint4*)&Bs[row * WSTRIDE + c4] = u;
    }
    __syncthreads();

    // ---- hoist b_hh ----
    float2 bhr = make_float2(0.f, 0.f), bhz = bhr, bhn = bhr;
    if (warp < 4) {
        bhr = *(const float2*)&b_hh[jc];
        bhz = *(const float2*)&b_hh[HH + jc];
        bhn = *(const float2*)&b_hh[2 * HH + jc];
    }

    for (int t = 0; t < TT; ++t) {
        const float* h_in  = g_h + (size_t)(t & 1) * (BB * HH);
        float*       h_out = g_h + (size_t)((t + 1) & 1) * (BB * HH);
        const float* xg_t  = g_xg + (size_t)t * BB * G3;
        float*       y_t   = g_y  + (size_t)t * BB * HH;
        const unsigned tgt = 16u * (unsigned)t;

        auto issue = [&](int slot, int c) {
#pragma unroll
            for (int i = 0; i < 8; ++i) {
                int e = tid + 256 * i;              // 2048 float4s per chunk
                int row = e >> 5, c4 = (e & 31) * 4;
                const float* src = h_in + row * HH + c * 128 + c4;
                unsigned dst = (unsigned)__cvta_generic_to_shared(
                    &As[(slot * 64 + row) * ACH + c4]);
                asm volatile("cp.async.cg.shared.global [%0], [%1], 16;"
                             :: "r"(dst), "l"(src));
            }
            asm volatile("cp.async.commit_group;" ::: "memory");
        };

        // wait for chunks 0,1 and own-chunk (for hold operands) to be produced
        if (tid == 0) {
            spin_acq(&g_flag[0],      tgt);
            spin_acq(&g_flag[1 * 32], tgt);
            spin_acq(&g_flag[cj * 32], tgt);
        }
        __syncthreads();

        issue(0, 0);
        issue(1, 1);

        // prefetch epilogue operands (overlap the GEMM)
        float2 xr0, xz0, xn0, xr1, xz1, xn1, hold0, hold1;
        if (warp < 4) {
            const float* xp0 = xg_t + (size_t)(r0 + gq) * G3 + jc;
            const float* xp1 = xg_t + (size_t)(r0 + gq + 8) * G3 + jc;
            xr0 = *(const float2*)(xp0);
            xz0 = *(const float2*)(xp0 + HH);
            xn0 = *(const float2*)(xp0 + 2 * HH);
            xr1 = *(const float2*)(xp1);
            xz1 = *(const float2*)(xp1 + HH);
            xn1 = *(const float2*)(xp1 + 2 * HH);
            hold0 = *(const float2*)&h_in[(r0 + gq) * HH + jc];
            hold1 = *(const float2*)&h_in[(r0 + gq + 8) * HH + jc];
        }

        float acc[3][4];
#pragma unroll
        for (int ni = 0; ni < 3; ++ni)
#pragma unroll
            for (int r = 0; r < 4; ++r) acc[ni][r] = 0.0f;

        for (int c = 0; c < 8; ++c) {
            if (c < 7) asm volatile("cp.async.wait_group 1;" ::: "memory");
            else       asm volatile("cp.async.wait_group 0;" ::: "memory");
            if (tid == 0 && c + 2 < 8) spin_acq(&g_flag[(c + 2) * 32], tgt);
            __syncthreads();                 // chunk c visible; slot (c+2)%3 free
            if (c + 2 < 8) issue((c + 2) % 3, c + 2);

            const int abase = (c % 3) * 64 * ACH;
            const int cb0   = c * 128;
#pragma unroll
            for (int kk = 0; kk < 8; ++kk) {
                const int ca = khalf * 64 + kk * 8 + 2 * t4;
                unsigned a[4];
                float2 x0 = *(const float2*)&As[abase + (r0 + gq) * ACH + ca];
                float2 x1 = *(const float2*)&As[abase + (r0 + gq + 8) * ACH + ca];
                a[0] = f2tf(x0.x); a[1] = f2tf(x1.x);
                a[2] = f2tf(x0.y); a[3] = f2tf(x1.y);
#pragma unroll
                for (int ni = 0; ni < 3; ++ni) {
                    uint2 bb = *(const uint2*)&Bs[(ni * 8 + gq) * WSTRIDE + cb0 + ca];
                    unsigned br[2] = { bb.x, bb.y };
                    mma8(acc[ni], a, br);
                }
            }
        }

        // ---- 2-way k reduction ----
        __syncthreads();
        if (warp >= 4) {
            float* dst = red + ((warp - 4) * 32 + lane) * 12;
#pragma unroll
            for (int ni = 0; ni < 3; ++ni)
#pragma unroll
                for (int r = 0; r < 4; ++r) dst[ni * 4 + r] = acc[ni][r];
        }
        __syncthreads();

        // ---- fused gate epilogue (warps 0-3) ----
        if (warp < 4) {
            const float* srcp = red + (warp * 32 + lane) * 12;
#pragma unroll
            for (int ni = 0; ni < 3; ++ni)
#pragma unroll
                for (int r = 0; r < 4; ++r) acc[ni][r] += srcp[ni * 4 + r];

            float r00 = sigmoidf_fast(xr0.x + acc[0][0] + bhr.x);
            float r01 = sigmoidf_fast(xr0.y + acc[0][1] + bhr.y);
            float r10 = sigmoidf_fast(xr1.x + acc[0][2] + bhr.x);
            float r11 = sigmoidf_fast(xr1.y + acc[0][3] + bhr.y);
            float z00 = sigmoidf_fast(xz0.x + acc[1][0] + bhz.x);
            float z01 = sigmoidf_fast(xz0.y + acc[1][1] + bhz.y);
            float z10 = sigmoidf_fast(xz1.x + acc[1][2] + bhz.x);
            float z11 = sigmoidf_fast(xz1.y + acc[1][3] + bhz.y);
            float n00 = tanhf(xn0.x + r00 * (acc[2][0] + bhn.x));
            float n01 = tanhf(xn0.y + r01 * (acc[2][1] + bhn.y));
            float n10 = tanhf(xn1.x + r10 * (acc[2][2] + bhn.x));
            float n11 = tanhf(xn1.y + r11 * (acc[2][3] + bhn.y));

            float2 o0 = make_float2((1.f - z00) * n00 + z00 * hold0.x,
                                    (1.f - z01) * n01 + z01 * hold0.y);
            float2 o1 = make_float2((1.f - z10) * n10 + z10 * hold1.x,
                                    (1.f - z11) * n11 + z11 * hold1.y);
            *(float2*)&h_out[(r0 + gq) * HH + jc]     = o0;
            *(float2*)&h_out[(r0 + gq + 8) * HH + jc] = o1;
            *(float2*)&y_t  [(r0 + gq) * HH + jc]     = o0;
            *(float2*)&y_t  [(r0 + gq + 8) * HH + jc] = o1;
            __threadfence();                // release h_out before flag post
        }

        // ---- post producer flag for this CTA's chunk ----
        __syncthreads();
        if (tid == 0) atomicAdd(&g_flag[cj * 32], 1u);
    }
}

// =====================================================================
// init hidden state (parity buffer 0) + reset producer flags
// =====================================================================
__global__ void copy_h(const float* __restrict__ src)
{
    int i = blockIdx.x * blockDim.x + threadIdx.x;
    if (i < BB * HH) g_h[i] = src[i];
    if (i < 8 * 32) g_flag[i] = 0;
}

// =====================================================================
// LayerNorm over last dim (1024), one block per row
// =====================================================================
__global__ __launch_bounds__(256)
void ln_kernel(const float* __restrict__ y, const float* __restrict__ gamma,
               const float* __restrict__ beta, float* __restrict__ out)
{
    __shared__ float sh[16];
    const size_t row = blockIdx.x;
    const int tid = threadIdx.x, lane = tid & 31, warp = tid >> 5;

    float4 v = ((const float4*)(y + row * HH))[tid];
    float s = v.x + v.y + v.z + v.w;
    float q = v.x * v.x + v.y * v.y + v.z * v.z + v.w * v.w;
#pragma unroll
    for (int o = 16; o > 0; o >>= 1) {
        s += __shfl_xor_sync(0xffffffffu, s, o);
        q += __shfl_xor_sync(0xffffffffu, q, o);
    }
    if (lane == 0) { sh[warp] = s; sh[8 + warp] = q; }
    __syncthreads();
    if (tid == 0) {
        float S = 0.0f, Q = 0.0f;
#pragma unroll
        for (int i = 0; i < 8; ++i) { S += sh[i]; Q += sh[8 + i]; }
        sh[0] = S; sh[8] = Q;
    }
    __syncthreads();
    const float mu   = sh[0] * (1.0f / HH);
    const float var  = sh[8] * (1.0f / HH) - mu * mu;
    const float rstd = rsqrtf(var + 1e-5f);

    float4 gm = ((const float4*)gamma)[tid];
    float4 bt = ((const float4*)beta)[tid];
    float4 o4;
    o4.x = (v.x - mu) * rstd * gm.x + bt.x;
    o4.y = (v.y - mu) * rstd * gm.y + bt.y;
    o4.z = (v.z - mu) * rstd * gm.z + bt.z;
    o4.w = (v.w - mu) * rstd * gm.w + bt.w;
    ((float4*)(out + row * HH))[tid] = o4;
}

// =====================================================================
// launcher  (8 graph nodes total)
// =====================================================================
extern "C" void kernel_launch(void* const* d_in, const int* in_sizes, int n_in,
                              void* d_out, int out_size)
{
    const float* x      = (const float*)d_in[0];
    const float* h      = (const float*)d_in[1];
    const float* w_ih0  = (const float*)d_in[2];
    const float* w_hh0  = (const float*)d_in[3];
    const float* b_ih0  = (const float*)d_in[4];
    const float* b_hh0  = (const float*)d_in[5];
    const float* w_ih1  = (const float*)d_in[6];
    const float* w_hh1  = (const float*)d_in[7];
    const float* b_ih1  = (const float*)d_in[8];
    const float* b_hh1  = (const float*)d_in[9];
    const float* ln_g   = (const float*)d_in[10];
    const float* ln_b   = (const float*)d_in[11];
    const float* ff_w   = (const float*)d_in[12];
    const float* ff_b   = (const float*)d_in[13];
    float* out = (float*)d_out;

    float* xg = nullptr;
    float* y  = nullptr;
    cudaGetSymbolAddress((void**)&xg, g_xg);
    cudaGetSymbolAddress((void**)&y,  g_y);

    const int smem_gru  = 24 * WSTRIDE * 4 + 3 * 64 * ACH * 4 + 4 * 32 * 12 * 4;
    const int smem_gemm = 3 * 2 * 128 * GST * 4;
    cudaFuncSetAttribute(gru_layer, cudaFuncAttributeMaxDynamicSharedMemorySize, smem_gru);
    cudaFuncSetAttribute(gemm_tn,   cudaFuncAttributeMaxDynamicSharedMemorySize, smem_gemm);

    // layer 0: input-side gate projections for all timesteps
    gemm_tn<<<dim3(G3 / 128, TBR / 128), 256, smem_gemm>>>(x, w_ih0, b_ih0, xg, TBR, G3, DIN);

    // layer 0 recurrence (persistent)
    copy_h<<<(BB * HH + 255) / 256, 256>>>(h);
    gru_layer<<<NCTA, 256, smem_gru>>>(w_hh0, b_hh0);

    // layer 1: input-side gate projections
    gemm_tn<<<dim3(G3 / 128, TBR / 128), 256, smem_gemm>>>(y, w_ih1, b_ih1, xg, TBR, G3, HH);

    // layer 1 recurrence (persistent)
    copy_h<<<(BB * HH + 255) / 256, 256>>>(h + BB * HH);
    gru_layer<<<NCTA, 256, smem_gru>>>(w_hh1, b_hh1);

    // LayerNorm (output reuses g_xg buffer)
    ln_kernel<<<TBR, 256>>>(y, ln_g, ln_b, xg);

    // output projection
    gemm_tn<<<dim3(DOUT / 128, TBR / 128), 256, smem_gemm>>>(xg, ff_w, ff_b, out, TBR, DOUT, HH);
}

// round 7
// speedup vs baseline: 1.2765x; 1.2765x over previous
#include <cuda_runtime.h>
#include <cstdint>

// ---------------- problem dims ----------------
#define TT   512
#define BB   64
#define DIN  512
#define HH   1024
#define G3   3072
#define DOUT 512
#define TBR  (TT*BB)     // 32768 rows

#define NCTA 128         // persistent kernel grid
#define JSL  8           // hidden columns per CTA (128*8 = 1024)

// ---------------- device scratch (no allocations allowed) ----------------
__device__ float g_xg[(size_t)TBR * G3];   // gate pre-activations (reused as LN output)
__device__ float g_y [(size_t)TBR * HH];   // layer output sequence
__device__ float g_h [2 * BB * HH];        // ping-pong hidden state
__device__ unsigned g_flag[8 * 32];        // per-chunk producer counters (128B padded)

// ---------------- helpers ----------------
__device__ __forceinline__ unsigned f2tf(float x) {
    unsigned r;
    asm("cvt.rna.tf32.f32 %0, %1;" : "=r"(r) : "f"(x));
    return r;
}

__device__ __forceinline__ void mma8(float* c, const unsigned* a, const unsigned* b) {
    asm volatile(
        "mma.sync.aligned.m16n8k8.row.col.f32.tf32.tf32.f32 "
        "{%0,%1,%2,%3},{%4,%5,%6,%7},{%8,%9},{%0,%1,%2,%3};"
        : "+f"(c[0]), "+f"(c[1]), "+f"(c[2]), "+f"(c[3])
        : "r"(a[0]), "r"(a[1]), "r"(a[2]), "r"(a[3]), "r"(b[0]), "r"(b[1]));
}

__device__ __forceinline__ float sigmoidf_fast(float x) {
    return 1.0f / (1.0f + __expf(-x));
}

// =====================================================================
// Generic GEMM: C[M,N] = A[M,K] * B[N,K]^T + bias[N]   (tf32 tensor cores)
// CTA tile 128x128, BK=32, 256 threads, warp tile 64x32, 2 CTAs/SM.
// (Round-4 version: fastest measured variant — co-resident CTAs hide
// each other's latency.) Requires M,N%128==0, K%32==0.
// =====================================================================
__global__ __launch_bounds__(256, 2)
void gemm_tn(const float* __restrict__ A, const float* __restrict__ B,
             const float* __restrict__ bias, float* __restrict__ C,
             int M, int N, int K)
{
    __shared__ unsigned As[128][40];
    __shared__ unsigned Bs[128][40];

    const int tid  = threadIdx.x;
    const int lane = tid & 31;
    const int warp = tid >> 5;
    const int wm   = (warp >> 2) * 64;   // warp grid 2 (M) x 4 (N)
    const int wn   = (warp & 3) * 32;
    const int gq   = lane >> 2;
    const int t4   = lane & 3;

    const int m0 = blockIdx.y * 128;
    const int n0 = blockIdx.x * 128;

    float c[4][4][4];
#pragma unroll
    for (int i = 0; i < 4; ++i)
#pragma unroll
        for (int j = 0; j < 4; ++j)
#pragma unroll
            for (int r = 0; r < 4; ++r) c[i][j][r] = 0.0f;

    for (int kt = 0; kt < K; kt += 32) {
        __syncthreads();
#pragma unroll
        for (int i = 0; i < 4; ++i) {
            int o   = tid + 256 * i;
            int row = o >> 3;
            int c4  = (o & 7) * 4;
            float4 v = *(const float4*)&A[(size_t)(m0 + row) * K + kt + c4];
            uint4 u; u.x = f2tf(v.x); u.y = f2tf(v.y); u.z = f2tf(v.z); u.w = f2tf(v.w);
            *(uint4*)&As[row][c4] = u;
        }
#pragma unroll
        for (int i = 0; i < 4; ++i) {
            int o   = tid + 256 * i;
            int row = o >> 3;
            int c4  = (o & 7) * 4;
            float4 v = *(const float4*)&B[(size_t)(n0 + row) * K + kt + c4];
            uint4 u; u.x = f2tf(v.x); u.y = f2tf(v.y); u.z = f2tf(v.z); u.w = f2tf(v.w);
            *(uint4*)&Bs[row][c4] = u;
        }
        __syncthreads();

#pragma unroll
        for (int kk = 0; kk < 4; ++kk) {
            const int cc = kk * 8 + 2 * t4;
            unsigned a[4][4], b[4][2];
#pragma unroll
            for (int mi = 0; mi < 4; ++mi) {
                int r0 = wm + mi * 16 + gq;
                uint2 x0 = *(const uint2*)&As[r0][cc];
                uint2 x1 = *(const uint2*)&As[r0 + 8][cc];
                a[mi][0] = x0.x; a[mi][1] = x1.x; a[mi][2] = x0.y; a[mi][3] = x1.y;
            }
#pragma unroll
            for (int ni = 0; ni < 4; ++ni) {
                int rn = wn + ni * 8 + gq;
                uint2 z0 = *(const uint2*)&Bs[rn][cc];
                b[ni][0] = z0.x; b[ni][1] = z0.y;
            }
#pragma unroll
            for (int mi = 0; mi < 4; ++mi)
#pragma unroll
                for (int ni = 0; ni < 4; ++ni)
                    mma8(c[mi][ni], a[mi], b[ni]);
        }
    }

#pragma unroll
    for (int mi = 0; mi < 4; ++mi) {
#pragma unroll
        for (int ni = 0; ni < 4; ++ni) {
            int row = m0 + wm + mi * 16 + gq;
            int col = n0 + wn + ni * 8 + 2 * t4;
            float b0 = bias[col], b1 = bias[col + 1];
            float2 v0 = make_float2(c[mi][ni][0] + b0, c[mi][ni][1] + b1);
            float2 v1 = make_float2(c[mi][ni][2] + b0, c[mi][ni][3] + b1);
            *(float2*)&C[(size_t)row * N + col]       = v0;
            *(float2*)&C[(size_t)(row + 8) * N + col] = v1;
        }
    }
}

// =====================================================================
// Persistent GRU layer kernel.
// grid = NCTA (128), 256 threads (8 warps). CTA b owns hidden cols
// [b*8, b*8+8). Weight slice (24 x 1024) smem-resident as tf32.
// Per step: h streamed via 3-slot cp.async ring of k=128 chunks.
// Step sync: each CTA posts ONE release-atomic to its chunk counter
// (16 CTAs/address, parallel across 8 addresses) after its epilogue;
// at step start threads 0-7 acquire-poll the 8 counters in parallel.
// =====================================================================
#define WSTRIDE 1032
#define ACH     136      // A chunk row stride (128 + 8)

__global__ __launch_bounds__(256, 1)
void gru_layer(const float* __restrict__ w_hh, const float* __restrict__ b_hh)
{
    extern __shared__ char smraw[];
    unsigned* Bs  = (unsigned*)smraw;                         // [24][WSTRIDE]
    float*    As  = (float*)(smraw + 24 * WSTRIDE * 4);       // [3][64][ACH]
    float*    red = As + 3 * 64 * ACH;                        // [4*32*12]

    const int tid   = threadIdx.x;
    const int lane  = tid & 31;
    const int warp  = tid >> 5;
    const int gq    = lane >> 2;
    const int t4    = lane & 3;
    const int mt    = warp & 3;          // M-tile id
    const int khalf = warp >> 2;         // K-half within each 128-chunk
    const int r0    = mt * 16;
    const int j0    = blockIdx.x * JSL;
    const int jc    = j0 + 2 * t4;
    const int cj    = j0 >> 7;           // chunk containing this CTA's columns

    // ---- preload weight slice (24 x 1024) as tf32 ----
    for (int e = tid; e < 24 * 256; e += 256) {
        int row = e >> 8;
        int c4  = (e & 255) * 4;
        int gate = row >> 3, jj = row & 7;
        float4 v = *(const float4*)&w_hh[(size_t)(gate * HH + j0 + jj) * HH + c4];
        uint4 u; u.x = f2tf(v.x); u.y = f2tf(v.y); u.z = f2tf(v.z); u.w = f2tf(v.w);
        *(uint4*)&Bs[row * WSTRIDE + c4] = u;
    }
    __syncthreads();

    // ---- hoist b_hh ----
    float2 bhr = make_float2(0.f, 0.f), bhz = bhr, bhn = bhr;
    if (warp < 4) {
        bhr = *(const float2*)&b_hh[jc];
        bhz = *(const float2*)&b_hh[HH + jc];
        bhn = *(const float2*)&b_hh[2 * HH + jc];
    }

    for (int t = 0; t < TT; ++t) {
        const float* h_in  = g_h + (size_t)(t & 1) * (BB * HH);
        float*       h_out = g_h + (size_t)((t + 1) & 1) * (BB * HH);
        const float* xg_t  = g_xg + (size_t)t * BB * G3;
        float*       y_t   = g_y  + (size_t)t * BB * HH;

        // ---- step barrier: wait for all 8 chunk groups of step t-1, in parallel ----
        if (tid < 8) {
            const unsigned tgt = 16u * (unsigned)t;
            const unsigned* fp = &g_flag[tid * 32];
            unsigned v;
            do {
                asm volatile("ld.acquire.gpu.global.u32 %0, [%1];" : "=r"(v) : "l"(fp));
            } while (v < tgt);
        }
        __syncthreads();

        auto issue = [&](int slot, int c) {
#pragma unroll
            for (int i = 0; i < 8; ++i) {
                int e = tid + 256 * i;              // 2048 float4s per chunk
                int row = e >> 5, c4 = (e & 31) * 4;
                const float* src = h_in + row * HH + c * 128 + c4;
                unsigned dst = (unsigned)__cvta_generic_to_shared(
                    &As[(slot * 64 + row) * ACH + c4]);
                asm volatile("cp.async.cg.shared.global [%0], [%1], 16;"
                             :: "r"(dst), "l"(src));
            }
            asm volatile("cp.async.commit_group;" ::: "memory");
        };

        issue(0, 0);
        issue(1, 1);

        // prefetch epilogue operands (overlap the GEMM)
        float2 xr0, xz0, xn0, xr1, xz1, xn1, hold0, hold1;
        if (warp < 4) {
            const float* xp0 = xg_t + (size_t)(r0 + gq) * G3 + jc;
            const float* xp1 = xg_t + (size_t)(r0 + gq + 8) * G3 + jc;
            xr0 = *(const float2*)(xp0);
            xz0 = *(const float2*)(xp0 + HH);
            xn0 = *(const float2*)(xp0 + 2 * HH);
            xr1 = *(const float2*)(xp1);
            xz1 = *(const float2*)(xp1 + HH);
            xn1 = *(const float2*)(xp1 + 2 * HH);
            hold0 = *(const float2*)&h_in[(r0 + gq) * HH + jc];
            hold1 = *(const float2*)&h_in[(r0 + gq + 8) * HH + jc];
        }

        float acc[3][4];
#pragma unroll
        for (int ni = 0; ni < 3; ++ni)
#pragma unroll
            for (int r = 0; r < 4; ++r) acc[ni][r] = 0.0f;

        for (int c = 0; c < 8; ++c) {
            if (c < 7) asm volatile("cp.async.wait_group 1;" ::: "memory");
            else       asm volatile("cp.async.wait_group 0;" ::: "memory");
            __syncthreads();                 // chunk c visible; slot (c+2)%3 free
            if (c + 2 < 8) issue((c + 2) % 3, c + 2);

            const int abase = (c % 3) * 64 * ACH;
            const int cb0   = c * 128;
#pragma unroll
            for (int kk = 0; kk < 8; ++kk) {
                const int ca = khalf * 64 + kk * 8 + 2 * t4;
                unsigned a[4];
                float2 x0 = *(const float2*)&As[abase + (r0 + gq) * ACH + ca];
                float2 x1 = *(const float2*)&As[abase + (r0 + gq + 8) * ACH + ca];
                a[0] = f2tf(x0.x); a[1] = f2tf(x1.x);
                a[2] = f2tf(x0.y); a[3] = f2tf(x1.y);
#pragma unroll
                for (int ni = 0; ni < 3; ++ni) {
                    uint2 bb = *(const uint2*)&Bs[(ni * 8 + gq) * WSTRIDE + cb0 + ca];
                    unsigned br[2] = { bb.x, bb.y };
                    mma8(acc[ni], a, br);
                }
            }
        }

        // ---- 2-way k reduction ----
        __syncthreads();
        if (warp >= 4) {
            float* dst = red + ((warp - 4) * 32 + lane) * 12;
#pragma unroll
            for (int ni = 0; ni < 3; ++ni)
#pragma unroll
                for (int r = 0; r < 4; ++r) dst[ni * 4 + r] = acc[ni][r];
        }
        __syncthreads();

        // ---- fused gate epilogue (warps 0-3) ----
        if (warp < 4) {
            const float* srcp = red + (warp * 32 + lane) * 12;
#pragma unroll
            for (int ni = 0; ni < 3; ++ni)
#pragma unroll
                for (int r = 0; r < 4; ++r) acc[ni][r] += srcp[ni * 4 + r];

            float r00 = sigmoidf_fast(xr0.x + acc[0][0] + bhr.x);
            float r01 = sigmoidf_fast(xr0.y + acc[0][1] + bhr.y);
            float r10 = sigmoidf_fast(xr1.x + acc[0][2] + bhr.x);
            float r11 = sigmoidf_fast(xr1.y + acc[0][3] + bhr.y);
            float z00 = sigmoidf_fast(xz0.x + acc[1][0] + bhz.x);
            float z01 = sigmoidf_fast(xz0.y + acc[1][1] + bhz.y);
            float z10 = sigmoidf_fast(xz1.x + acc[1][2] + bhz.x);
            float z11 = sigmoidf_fast(xz1.y + acc[1][3] + bhz.y);
            float n00 = tanhf(xn0.x + r00 * (acc[2][0] + bhn.x));
            float n01 = tanhf(xn0.y + r01 * (acc[2][1] + bhn.y));
            float n10 = tanhf(xn1.x + r10 * (acc[2][2] + bhn.x));
            float n11 = tanhf(xn1.y + r11 * (acc[2][3] + bhn.y));

            float2 o0 = make_float2((1.f - z00) * n00 + z00 * hold0.x,
                                    (1.f - z01) * n01 + z01 * hold0.y);
            float2 o1 = make_float2((1.f - z10) * n10 + z10 * hold1.x,
                                    (1.f - z11) * n11 + z11 * hold1.y);
            *(float2*)&h_out[(r0 + gq) * HH + jc]     = o0;
            *(float2*)&h_out[(r0 + gq + 8) * HH + jc] = o1;
            *(float2*)&y_t  [(r0 + gq) * HH + jc]     = o0;
            *(float2*)&y_t  [(r0 + gq + 8) * HH + jc] = o1;
        }

        // ---- publish: syncthreads gives happens-before; one release atomic ----
        __syncthreads();
        if (tid == 0) {
            asm volatile("red.release.gpu.global.add.u32 [%0], %1;"
                         :: "l"(&g_flag[cj * 32]), "r"(1u) : "memory");
        }
    }
}

// =====================================================================
// init hidden state (parity buffer 0) + reset producer flags
// =====================================================================
__global__ void copy_h(const float* __restrict__ src)
{
    int i = blockIdx.x * blockDim.x + threadIdx.x;
    if (i < BB * HH) g_h[i] = src[i];
    if (i < 8 * 32) g_flag[i] = 0;
}

// =====================================================================
// LayerNorm over last dim (1024), one block per row
// =====================================================================
__global__ __launch_bounds__(256)
void ln_kernel(const float* __restrict__ y, const float* __restrict__ gamma,
               const float* __restrict__ beta, float* __restrict__ out)
{
    __shared__ float sh[16];
    const size_t row = blockIdx.x;
    const int tid = threadIdx.x, lane = tid & 31, warp = tid >> 5;

    float4 v = ((const float4*)(y + row * HH))[tid];
    float s = v.x + v.y + v.z + v.w;
    float q = v.x * v.x + v.y * v.y + v.z * v.z + v.w * v.w;
#pragma unroll
    for (int o = 16; o > 0; o >>= 1) {
        s += __shfl_xor_sync(0xffffffffu, s, o);
        q += __shfl_xor_sync(0xffffffffu, q, o);
    }
    if (lane == 0) { sh[warp] = s; sh[8 + warp] = q; }
    __syncthreads();
    if (tid == 0) {
        float S = 0.0f, Q = 0.0f;
#pragma unroll
        for (int i = 0; i < 8; ++i) { S += sh[i]; Q += sh[8 + i]; }
        sh[0] = S; sh[8] = Q;
    }
    __syncthreads();
    const float mu   = sh[0] * (1.0f / HH);
    const float var  = sh[8] * (1.0f / HH) - mu * mu;
    const float rstd = rsqrtf(var + 1e-5f);

    float4 gm = ((const float4*)gamma)[tid];
    float4 bt = ((const float4*)beta)[tid];
    float4 o4;
    o4.x = (v.x - mu) * rstd * gm.x + bt.x;
    o4.y = (v.y - mu) * rstd * gm.y + bt.y;
    o4.z = (v.z - mu) * rstd * gm.z + bt.z;
    o4.w = (v.w - mu) * rstd * gm.w + bt.w;
    ((float4*)(out + row * HH))[tid] = o4;
}

// =====================================================================
// launcher  (8 graph nodes total)
// =====================================================================
extern "C" void kernel_launch(void* const* d_in, const int* in_sizes, int n_in,
                              void* d_out, int out_size)
{
    const float* x      = (const float*)d_in[0];
    const float* h      = (const float*)d_in[1];
    const float* w_ih0  = (const float*)d_in[2];
    const float* w_hh0  = (const float*)d_in[3];
    const float* b_ih0  = (const float*)d_in[4];
    const float* b_hh0  = (const float*)d_in[5];
    const float* w_ih1  = (const float*)d_in[6];
    const float* w_hh1  = (const float*)d_in[7];
    const float* b_ih1  = (const float*)d_in[8];
    const float* b_hh1  = (const float*)d_in[9];
    const float* ln_g   = (const float*)d_in[10];
    const float* ln_b   = (const float*)d_in[11];
    const float* ff_w   = (const float*)d_in[12];
    const float* ff_b   = (const float*)d_in[13];
    float* out = (float*)d_out;

    float* xg = nullptr;
    float* y  = nullptr;
    cudaGetSymbolAddress((void**)&xg, g_xg);
    cudaGetSymbolAddress((void**)&y,  g_y);

    const int smem_gru = 24 * WSTRIDE * 4 + 3 * 64 * ACH * 4 + 4 * 32 * 12 * 4;
    cudaFuncSetAttribute(gru_layer, cudaFuncAttributeMaxDynamicSharedMemorySize, smem_gru);

    // layer 0: input-side gate projections for all timesteps
    gemm_tn<<<dim3(G3 / 128, TBR / 128), 256>>>(x, w_ih0, b_ih0, xg, TBR, G3, DIN);

    // layer 0 recurrence (persistent)
    copy_h<<<(BB * HH + 255) / 256, 256>>>(h);
    gru_layer<<<NCTA, 256, smem_gru>>>(w_hh0, b_hh0);

    // layer 1: input-side gate projections
    gemm_tn<<<dim3(G3 / 128, TBR / 128), 256>>>(y, w_ih1, b_ih1, xg, TBR, G3, HH);

    // layer 1 recurrence (persistent)
    copy_h<<<(BB * HH + 255) / 256, 256>>>(h + BB * HH);
    gru_layer<<<NCTA, 256, smem_gru>>>(w_hh1, b_hh1);

    // LayerNorm (output reuses g_xg buffer)
    ln_kernel<<<TBR, 256>>>(y, ln_g, ln_b, xg);

    // output projection
    gemm_tn<<<dim3(DOUT / 128, TBR / 128), 256>>>(xg, ff_w, ff_b, out, TBR, DOUT, HH);
}

// round 8
// speedup vs baseline: 1.3013x; 1.0194x over previous
#include <cuda_runtime.h>
#include <cstdint>

// ---------------- problem dims ----------------
#define TT   512
#define BB   64
#define DIN  512
#define HH   1024
#define G3   3072
#define DOUT 512
#define TBR  (TT*BB)     // 32768 rows

#define NCTA 128         // persistent kernel grid
#define JSL  8           // hidden columns per CTA (128*8 = 1024)

// ---------------- device scratch (no allocations allowed) ----------------
__device__ float g_xg[(size_t)TBR * G3];   // gate pre-activations (reused as LN output)
__device__ float g_y [(size_t)TBR * HH];   // layer output sequence
__device__ float g_h [2 * BB * HH];        // ping-pong hidden state
__device__ unsigned g_flag[8 * 32];        // per-chunk producer counters (128B padded)

// ---------------- helpers ----------------
__device__ __forceinline__ unsigned f2tf(float x) {
    unsigned r;
    asm("cvt.rna.tf32.f32 %0, %1;" : "=r"(r) : "f"(x));
    return r;
}

__device__ __forceinline__ void mma8(float* c, const unsigned* a, const unsigned* b) {
    asm volatile(
        "mma.sync.aligned.m16n8k8.row.col.f32.tf32.tf32.f32 "
        "{%0,%1,%2,%3},{%4,%5,%6,%7},{%8,%9},{%0,%1,%2,%3};"
        : "+f"(c[0]), "+f"(c[1]), "+f"(c[2]), "+f"(c[3])
        : "r"(a[0]), "r"(a[1]), "r"(a[2]), "r"(a[3]), "r"(b[0]), "r"(b[1]));
}

__device__ __forceinline__ float sigmoidf_fast(float x) {
    return 1.0f / (1.0f + __expf(-x));
}

// =====================================================================
// Generic GEMM: C[M,N] = A[M,K] * B[N,K]^T + bias[N]   (tf32 tensor cores)
// CTA tile 128x128, BK=32, 256 threads, warp tile 64x32.
// 2-stage cp.async double buffer (80 KB dynamic smem) so TWO CTAs stay
// co-resident per SM; consumer-side tf32 conversion.
// Requires M,N%128==0, K%64==0.
// =====================================================================
#define GST 40           // smem row stride in floats (mod 32 == 8, conflict-free)

__global__ __launch_bounds__(256, 2)
void gemm_tn(const float* __restrict__ A, const float* __restrict__ B,
             const float* __restrict__ bias, float* __restrict__ C,
             int M, int N, int K)
{
    extern __shared__ float gsm[];
    float* As = gsm;                         // [2][128][GST]
    float* Bs = gsm + 2 * 128 * GST;         // [2][128][GST]

    const int tid  = threadIdx.x;
    const int lane = tid & 31;
    const int warp = tid >> 5;
    const int wm   = (warp >> 2) * 64;   // warp grid 2 (M) x 4 (N)
    const int wn   = (warp & 3) * 32;
    const int gq   = lane >> 2;
    const int t4   = lane & 3;

    const int m0 = blockIdx.y * 128;
    const int n0 = blockIdx.x * 128;

    const int ld_row = tid >> 3;          // 0..31 (x4 strided covers 128 rows)
    const int ld_c4  = (tid & 7) * 4;

    const int nk = K / 32;

    auto issue = [&](int slot, int i) {
        const int kt = i * 32;
#pragma unroll
        for (int r = 0; r < 4; ++r) {
            int row = ld_row + 32 * r;
            const float* srcA = &A[(size_t)(m0 + row) * K + kt + ld_c4];
            const float* srcB = &B[(size_t)(n0 + row) * K + kt + ld_c4];
            unsigned dA = (unsigned)__cvta_generic_to_shared(
                &As[(slot * 128 + row) * GST + ld_c4]);
            unsigned dB = (unsigned)__cvta_generic_to_shared(
                &Bs[(slot * 128 + row) * GST + ld_c4]);
            asm volatile("cp.async.cg.shared.global [%0], [%1], 16;" :: "r"(dA), "l"(srcA));
            asm volatile("cp.async.cg.shared.global [%0], [%1], 16;" :: "r"(dB), "l"(srcB));
        }
        asm volatile("cp.async.commit_group;" ::: "memory");
    };

    float c[4][4][4];
#pragma unroll
    for (int i = 0; i < 4; ++i)
#pragma unroll
        for (int j = 0; j < 4; ++j)
#pragma unroll
            for (int r = 0; r < 4; ++r) c[i][j][r] = 0.0f;

    issue(0, 0);
    issue(1, 1);

    for (int i = 0; i < nk; ++i) {
        if (i + 1 < nk) asm volatile("cp.async.wait_group 1;" ::: "memory");
        else            asm volatile("cp.async.wait_group 0;" ::: "memory");
        __syncthreads();                      // tile i visible to all threads

        const float* as = As + (i & 1) * 128 * GST;
        const float* bs = Bs + (i & 1) * 128 * GST;
#pragma unroll
        for (int kk = 0; kk < 4; ++kk) {
            const int cc = kk * 8 + 2 * t4;
            unsigned a[4][4], b[4][2];
#pragma unroll
            for (int mi = 0; mi < 4; ++mi) {
                int r0 = wm + mi * 16 + gq;
                float2 x0 = *(const float2*)&as[r0 * GST + cc];
                float2 x1 = *(const float2*)&as[(r0 + 8) * GST + cc];
                a[mi][0] = f2tf(x0.x); a[mi][1] = f2tf(x1.x);
                a[mi][2] = f2tf(x0.y); a[mi][3] = f2tf(x1.y);
            }
#pragma unroll
            for (int ni = 0; ni < 4; ++ni) {
                float2 z = *(const float2*)&bs[(wn + ni * 8 + gq) * GST + cc];
                b[ni][0] = f2tf(z.x); b[ni][1] = f2tf(z.y);
            }
#pragma unroll
            for (int mi = 0; mi < 4; ++mi)
#pragma unroll
                for (int ni = 0; ni < 4; ++ni)
                    mma8(c[mi][ni], a[mi], b[ni]);
        }

        __syncthreads();                      // all done reading slot i&1
        if (i + 2 < nk) issue(i & 1, i + 2);  // overwrite the freed slot
    }

    // epilogue: C = acc + bias
#pragma unroll
    for (int mi = 0; mi < 4; ++mi) {
#pragma unroll
        for (int ni = 0; ni < 4; ++ni) {
            int row = m0 + wm + mi * 16 + gq;
            int col = n0 + wn + ni * 8 + 2 * t4;
            float b0 = bias[col], b1 = bias[col + 1];
            float2 v0 = make_float2(c[mi][ni][0] + b0, c[mi][ni][1] + b1);
            float2 v1 = make_float2(c[mi][ni][2] + b0, c[mi][ni][3] + b1);
            *(float2*)&C[(size_t)row * N + col]       = v0;
            *(float2*)&C[(size_t)(row + 8) * N + col] = v1;
        }
    }
}

// =====================================================================
// Persistent GRU layer kernel.
// grid = NCTA (128), 256 threads (8 warps). CTA b owns hidden cols
// [b*8, b*8+8). Weight slice (24 x 1024) smem-resident as tf32.
// Per step: h streamed via 3-slot cp.async ring of k=128 chunks.
// Step sync: one release-atomic per CTA to its chunk counter; at step
// start threads 0-7 acquire-poll the 8 counters in parallel. xg-side
// epilogue operands are prefetched BEFORE the barrier (always ready).
// =====================================================================
#define WSTRIDE 1032
#define ACH     136      // A chunk row stride (128 + 8)

__global__ __launch_bounds__(256, 1)
void gru_layer(const float* __restrict__ w_hh, const float* __restrict__ b_hh)
{
    extern __shared__ char smraw[];
    unsigned* Bs  = (unsigned*)smraw;                         // [24][WSTRIDE]
    float*    As  = (float*)(smraw + 24 * WSTRIDE * 4);       // [3][64][ACH]
    float*    red = As + 3 * 64 * ACH;                        // [4*32*12]

    const int tid   = threadIdx.x;
    const int lane  = tid & 31;
    const int warp  = tid >> 5;
    const int gq    = lane >> 2;
    const int t4    = lane & 3;
    const int mt    = warp & 3;          // M-tile id
    const int khalf = warp >> 2;         // K-half within each 128-chunk
    const int r0    = mt * 16;
    const int j0    = blockIdx.x * JSL;
    const int jc    = j0 + 2 * t4;
    const int cj    = j0 >> 7;           // chunk containing this CTA's columns

    // ---- preload weight slice (24 x 1024) as tf32 ----
    for (int e = tid; e < 24 * 256; e += 256) {
        int row = e >> 8;
        int c4  = (e & 255) * 4;
        int gate = row >> 3, jj = row & 7;
        float4 v = *(const float4*)&w_hh[(size_t)(gate * HH + j0 + jj) * HH + c4];
        uint4 u; u.x = f2tf(v.x); u.y = f2tf(v.y); u.z = f2tf(v.z); u.w = f2tf(v.w);
        *(uint4*)&Bs[row * WSTRIDE + c4] = u;
    }
    __syncthreads();

    // ---- hoist b_hh ----
    float2 bhr = make_float2(0.f, 0.f), bhz = bhr, bhn = bhr;
    if (warp < 4) {
        bhr = *(const float2*)&b_hh[jc];
        bhz = *(const float2*)&b_hh[HH + jc];
        bhn = *(const float2*)&b_hh[2 * HH + jc];
    }

    for (int t = 0; t < TT; ++t) {
        const float* h_in  = g_h + (size_t)(t & 1) * (BB * HH);
        float*       h_out = g_h + (size_t)((t + 1) & 1) * (BB * HH);
        const float* xg_t  = g_xg + (size_t)t * BB * G3;
        float*       y_t   = g_y  + (size_t)t * BB * HH;

        // ---- prefetch xg operands BEFORE the barrier (always ready) ----
        float2 xr0, xz0, xn0, xr1, xz1, xn1, hold0, hold1;
        if (warp < 4) {
            const float* xp0 = xg_t + (size_t)(r0 + gq) * G3 + jc;
            const float* xp1 = xg_t + (size_t)(r0 + gq + 8) * G3 + jc;
            xr0 = *(const float2*)(xp0);
            xz0 = *(const float2*)(xp0 + HH);
            xn0 = *(const float2*)(xp0 + 2 * HH);
            xr1 = *(const float2*)(xp1);
            xz1 = *(const float2*)(xp1 + HH);
            xn1 = *(const float2*)(xp1 + 2 * HH);
        }

        // ---- step barrier: wait for all 8 chunk groups of step t-1, in parallel ----
        if (tid < 8) {
            const unsigned tgt = 16u * (unsigned)t;
            const unsigned* fp = &g_flag[tid * 32];
            unsigned v;
            do {
                asm volatile("ld.acquire.gpu.global.u32 %0, [%1];" : "=r"(v) : "l"(fp));
            } while (v < tgt);
        }
        __syncthreads();

        auto issue = [&](int slot, int c) {
#pragma unroll
            for (int i = 0; i < 8; ++i) {
                int e = tid + 256 * i;              // 2048 float4s per chunk
                int row = e >> 5, c4 = (e & 31) * 4;
                const float* src = h_in + row * HH + c * 128 + c4;
                unsigned dst = (unsigned)__cvta_generic_to_shared(
                    &As[(slot * 64 + row) * ACH + c4]);
                asm volatile("cp.async.cg.shared.global [%0], [%1], 16;"
                             :: "r"(dst), "l"(src));
            }
            asm volatile("cp.async.commit_group;" ::: "memory");
        };

        issue(0, 0);
        issue(1, 1);

        // h-side epilogue operands (must be after the barrier)
        if (warp < 4) {
            hold0 = *(const float2*)&h_in[(r0 + gq) * HH + jc];
            hold1 = *(const float2*)&h_in[(r0 + gq + 8) * HH + jc];
        }

        float acc[3][4];
#pragma unroll
        for (int ni = 0; ni < 3; ++ni)
#pragma unroll
            for (int r = 0; r < 4; ++r) acc[ni][r] = 0.0f;

        for (int c = 0; c < 8; ++c) {
            if (c < 7) asm volatile("cp.async.wait_group 1;" ::: "memory");
            else       asm volatile("cp.async.wait_group 0;" ::: "memory");
            __syncthreads();                 // chunk c visible; slot (c+2)%3 free
            if (c + 2 < 8) issue((c + 2) % 3, c + 2);

            const int abase = (c % 3) * 64 * ACH;
            const int cb0   = c * 128;
#pragma unroll
            for (int kk = 0; kk < 8; ++kk) {
                const int ca = khalf * 64 + kk * 8 + 2 * t4;
                unsigned a[4];
                float2 x0 = *(const float2*)&As[abase + (r0 + gq) * ACH + ca];
                float2 x1 = *(const float2*)&As[abase + (r0 + gq + 8) * ACH + ca];
                a[0] = f2tf(x0.x); a[1] = f2tf(x1.x);
                a[2] = f2tf(x0.y); a[3] = f2tf(x1.y);
#pragma unroll
                for (int ni = 0; ni < 3; ++ni) {
                    uint2 bb = *(const uint2*)&Bs[(ni * 8 + gq) * WSTRIDE + cb0 + ca];
                    unsigned br[2] = { bb.x, bb.y };
                    mma8(acc[ni], a, br);
                }
            }
        }

        // ---- 2-way k reduction ----
        __syncthreads();
        if (warp >= 4) {
            float* dst = red + ((warp - 4) * 32 + lane) * 12;
#pragma unroll
            for (int ni = 0; ni < 3; ++ni)
#pragma unroll
                for (int r = 0; r < 4; ++r) dst[ni * 4 + r] = acc[ni][r];
        }
        __syncthreads();

        // ---- fused gate epilogue (warps 0-3) ----
        if (warp < 4) {
            const float* srcp = red + (warp * 32 + lane) * 12;
#pragma unroll
            for (int ni = 0; ni < 3; ++ni)
#pragma unroll
                for (int r = 0; r < 4; ++r) acc[ni][r] += srcp[ni * 4 + r];

            float r00 = sigmoidf_fast(xr0.x + acc[0][0] + bhr.x);
            float r01 = sigmoidf_fast(xr0.y + acc[0][1] + bhr.y);
            float r10 = sigmoidf_fast(xr1.x + acc[0][2] + bhr.x);
            float r11 = sigmoidf_fast(xr1.y + acc[0][3] + bhr.y);
            float z00 = sigmoidf_fast(xz0.x + acc[1][0] + bhz.x);
            float z01 = sigmoidf_fast(xz0.y + acc[1][1] + bhz.y);
            float z10 = sigmoidf_fast(xz1.x + acc[1][2] + bhz.x);
            float z11 = sigmoidf_fast(xz1.y + acc[1][3] + bhz.y);
            float n00 = tanhf(xn0.x + r00 * (acc[2][0] + bhn.x));
            float n01 = tanhf(xn0.y + r01 * (acc[2][1] + bhn.y));
            float n10 = tanhf(xn1.x + r10 * (acc[2][2] + bhn.x));
            float n11 = tanhf(xn1.y + r11 * (acc[2][3] + bhn.y));

            float2 o0 = make_float2((1.f - z00) * n00 + z00 * hold0.x,
                                    (1.f - z01) * n01 + z01 * hold0.y);
            float2 o1 = make_float2((1.f - z10) * n10 + z10 * hold1.x,
                                    (1.f - z11) * n11 + z11 * hold1.y);
            *(float2*)&h_out[(r0 + gq) * HH + jc]     = o0;
            *(float2*)&h_out[(r0 + gq + 8) * HH + jc] = o1;
            *(float2*)&y_t  [(r0 + gq) * HH + jc]     = o0;
            *(float2*)&y_t  [(r0 + gq + 8) * HH + jc] = o1;
        }

        // ---- publish: syncthreads gives happens-before; one release atomic ----
        __syncthreads();
        if (tid == 0) {
            asm volatile("red.release.gpu.global.add.u32 [%0], %1;"
                         :: "l"(&g_flag[cj * 32]), "r"(1u) : "memory");
        }
    }
}

// =====================================================================
// init hidden state (parity buffer 0) + reset producer flags
// =====================================================================
__global__ void copy_h(const float* __restrict__ src)
{
    int i = blockIdx.x * blockDim.x + threadIdx.x;
    if (i < BB * HH) g_h[i] = src[i];
    if (i < 8 * 32) g_flag[i] = 0;
}

// =====================================================================
// LayerNorm over last dim (1024), one block per row
// =====================================================================
__global__ __launch_bounds__(256)
void ln_kernel(const float* __restrict__ y, const float* __restrict__ gamma,
               const float* __restrict__ beta, float* __restrict__ out)
{
    __shared__ float sh[16];
    const size_t row = blockIdx.x;
    const int tid = threadIdx.x, lane = tid & 31, warp = tid >> 5;

    float4 v = ((const float4*)(y + row * HH))[tid];
    float s = v.x + v.y + v.z + v.w;
    float q = v.x * v.x + v.y * v.y + v.z * v.z + v.w * v.w;
#pragma unroll
    for (int o = 16; o > 0; o >>= 1) {
        s += __shfl_xor_sync(0xffffffffu, s, o);
        q += __shfl_xor_sync(0xffffffffu, q, o);
    }
    if (lane == 0) { sh[warp] = s; sh[8 + warp] = q; }
    __syncthreads();
    if (tid == 0) {
        float S = 0.0f, Q = 0.0f;
#pragma unroll
        for (int i = 0; i < 8; ++i) { S += sh[i]; Q += sh[8 + i]; }
        sh[0] = S; sh[8] = Q;
    }
    __syncthreads();
    const float mu   = sh[0] * (1.0f / HH);
    const float var  = sh[8] * (1.0f / HH) - mu * mu;
    const float rstd = rsqrtf(var + 1e-5f);

    float4 gm = ((const float4*)gamma)[tid];
    float4 bt = ((const float4*)beta)[tid];
    float4 o4;
    o4.x = (v.x - mu) * rstd * gm.x + bt.x;
    o4.y = (v.y - mu) * rstd * gm.y + bt.y;
    o4.z = (v.z - mu) * rstd * gm.z + bt.z;
    o4.w = (v.w - mu) * rstd * gm.w + bt.w;
    ((float4*)(out + row * HH))[tid] = o4;
}

// =====================================================================
// launcher  (8 graph nodes total)
// =====================================================================
extern "C" void kernel_launch(void* const* d_in, const int* in_sizes, int n_in,
                              void* d_out, int out_size)
{
    const float* x      = (const float*)d_in[0];
    const float* h      = (const float*)d_in[1];
    const float* w_ih0  = (const float*)d_in[2];
    const float* w_hh0  = (const float*)d_in[3];
    const float* b_ih0  = (const float*)d_in[4];
    const float* b_hh0  = (const float*)d_in[5];
    const float* w_ih1  = (const float*)d_in[6];
    const float* w_hh1  = (const float*)d_in[7];
    const float* b_ih1  = (const float*)d_in[8];
    const float* b_hh1  = (const float*)d_in[9];
    const float* ln_g   = (const float*)d_in[10];
    const float* ln_b   = (const float*)d_in[11];
    const float* ff_w   = (const float*)d_in[12];
    const float* ff_b   = (const float*)d_in[13];
    float* out = (float*)d_out;

    float* xg = nullptr;
    float* y  = nullptr;
    cudaGetSymbolAddress((void**)&xg, g_xg);
    cudaGetSymbolAddress((void**)&y,  g_y);

    const int smem_gru  = 24 * WSTRIDE * 4 + 3 * 64 * ACH * 4 + 4 * 32 * 12 * 4;
    const int smem_gemm = 2 * 2 * 128 * GST * 4;   // 81920 B (2 CTAs/SM)
    cudaFuncSetAttribute(gru_layer, cudaFuncAttributeMaxDynamicSharedMemorySize, smem_gru);
    cudaFuncSetAttribute(gemm_tn,   cudaFuncAttributeMaxDynamicSharedMemorySize, smem_gemm);

    // layer 0: input-side gate projections for all timesteps
    gemm_tn<<<dim3(G3 / 128, TBR / 128), 256, smem_gemm>>>(x, w_ih0, b_ih0, xg, TBR, G3, DIN);

    // layer 0 recurrence (persistent)
    copy_h<<<(BB * HH + 255) / 256, 256>>>(h);
    gru_layer<<<NCTA, 256, smem_gru>>>(w_hh0, b_hh0);

    // layer 1: input-side gate projections
    gemm_tn<<<dim3(G3 / 128, TBR / 128), 256, smem_gemm>>>(y, w_ih1, b_ih1, xg, TBR, G3, HH);

    // layer 1 recurrence (persistent)
    copy_h<<<(BB * HH + 255) / 256, 256>>>(h + BB * HH);
    gru_layer<<<NCTA, 256, smem_gru>>>(w_hh1, b_hh1);

    // LayerNorm (output reuses g_xg buffer)
    ln_kernel<<<TBR, 256>>>(y, ln_g, ln_b, xg);

    // output projection
    gemm_tn<<<dim3(DOUT / 128, TBR / 128), 256, smem_gemm>>>(xg, ff_w, ff_b, out, TBR, DOUT, HH);
}

// round 9
// speedup vs baseline: 1.4543x; 1.1176x over previous
#include <cuda_runtime.h>
#include <cstdint>

// ---------------- problem dims ----------------
#define TT   512
#define BB   64
#define DIN  512
#define HH   1024
#define G3   3072
#define DOUT 512
#define TBR  (TT*BB)     // 32768 rows

#define NCTA 128         // persistent kernel grid
#define JSL  8           // hidden columns per CTA (128*8 = 1024)

// ---------------- device scratch (no allocations allowed) ----------------
__device__ float g_xg[(size_t)TBR * G3];   // gate pre-activations (reused as LN output)
__device__ float g_y [(size_t)TBR * HH];   // layer output sequence
__device__ float g_h [2 * BB * HH];        // ping-pong hidden state
__device__ unsigned g_flag[8 * 32];        // per-chunk producer counters (128B padded)

// ---------------- helpers ----------------
__device__ __forceinline__ unsigned f2tf(float x) {
    unsigned r;
    asm("cvt.rna.tf32.f32 %0, %1;" : "=r"(r) : "f"(x));
    return r;
}

__device__ __forceinline__ void mma8(float* c, const unsigned* a, const unsigned* b) {
    asm volatile(
        "mma.sync.aligned.m16n8k8.row.col.f32.tf32.tf32.f32 "
        "{%0,%1,%2,%3},{%4,%5,%6,%7},{%8,%9},{%0,%1,%2,%3};"
        : "+f"(c[0]), "+f"(c[1]), "+f"(c[2]), "+f"(c[3])
        : "r"(a[0]), "r"(a[1]), "r"(a[2]), "r"(a[3]), "r"(b[0]), "r"(b[1]));
}

__device__ __forceinline__ float sigmoid_fast(float x) {
    return __fdividef(1.0f, 1.0f + __expf(-x));
}

__device__ __forceinline__ float tanh_fast(float x) {
    x = fminf(fmaxf(x, -15.0f), 15.0f);
    float t = __expf(2.0f * x);
    return __fdividef(t - 1.0f, t + 1.0f);
}

// =====================================================================
// Generic GEMM: C[M,N] = A[M,K] * B[N,K]^T + bias[N]   (tf32 tensor cores)
// CTA tile 128x128, BK=32, 256 threads, warp tile 64x32, 2 CTAs/SM.
// (Round-4 version — fastest measured.) Requires M,N%128==0, K%32==0.
// =====================================================================
__global__ __launch_bounds__(256, 2)
void gemm_tn(const float* __restrict__ A, const float* __restrict__ B,
             const float* __restrict__ bias, float* __restrict__ C,
             int M, int N, int K)
{
    __shared__ unsigned As[128][40];
    __shared__ unsigned Bs[128][40];

    const int tid  = threadIdx.x;
    const int lane = tid & 31;
    const int warp = tid >> 5;
    const int wm   = (warp >> 2) * 64;   // warp grid 2 (M) x 4 (N)
    const int wn   = (warp & 3) * 32;
    const int gq   = lane >> 2;
    const int t4   = lane & 3;

    const int m0 = blockIdx.y * 128;
    const int n0 = blockIdx.x * 128;

    float c[4][4][4];
#pragma unroll
    for (int i = 0; i < 4; ++i)
#pragma unroll
        for (int j = 0; j < 4; ++j)
#pragma unroll
            for (int r = 0; r < 4; ++r) c[i][j][r] = 0.0f;

    for (int kt = 0; kt < K; kt += 32) {
        __syncthreads();
#pragma unroll
        for (int i = 0; i < 4; ++i) {
            int o   = tid + 256 * i;
            int row = o >> 3;
            int c4  = (o & 7) * 4;
            float4 v = *(const float4*)&A[(size_t)(m0 + row) * K + kt + c4];
            uint4 u; u.x = f2tf(v.x); u.y = f2tf(v.y); u.z = f2tf(v.z); u.w = f2tf(v.w);
            *(uint4*)&As[row][c4] = u;
        }
#pragma unroll
        for (int i = 0; i < 4; ++i) {
            int o   = tid + 256 * i;
            int row = o >> 3;
            int c4  = (o & 7) * 4;
            float4 v = *(const float4*)&B[(size_t)(n0 + row) * K + kt + c4];
            uint4 u; u.x = f2tf(v.x); u.y = f2tf(v.y); u.z = f2tf(v.z); u.w = f2tf(v.w);
            *(uint4*)&Bs[row][c4] = u;
        }
        __syncthreads();

#pragma unroll
        for (int kk = 0; kk < 4; ++kk) {
            const int cc = kk * 8 + 2 * t4;
            unsigned a[4][4], b[4][2];
#pragma unroll
            for (int mi = 0; mi < 4; ++mi) {
                int r0 = wm + mi * 16 + gq;
                uint2 x0 = *(const uint2*)&As[r0][cc];
                uint2 x1 = *(const uint2*)&As[r0 + 8][cc];
                a[mi][0] = x0.x; a[mi][1] = x1.x; a[mi][2] = x0.y; a[mi][3] = x1.y;
            }
#pragma unroll
            for (int ni = 0; ni < 4; ++ni) {
                int rn = wn + ni * 8 + gq;
                uint2 z0 = *(const uint2*)&Bs[rn][cc];
                b[ni][0] = z0.x; b[ni][1] = z0.y;
            }
#pragma unroll
            for (int mi = 0; mi < 4; ++mi)
#pragma unroll
                for (int ni = 0; ni < 4; ++ni)
                    mma8(c[mi][ni], a[mi], b[ni]);
        }
    }

#pragma unroll
    for (int mi = 0; mi < 4; ++mi) {
#pragma unroll
        for (int ni = 0; ni < 4; ++ni) {
            int row = m0 + wm + mi * 16 + gq;
            int col = n0 + wn + ni * 8 + 2 * t4;
            float b0 = bias[col], b1 = bias[col + 1];
            float2 v0 = make_float2(c[mi][ni][0] + b0, c[mi][ni][1] + b1);
            float2 v1 = make_float2(c[mi][ni][2] + b0, c[mi][ni][3] + b1);
            *(float2*)&C[(size_t)row * N + col]       = v0;
            *(float2*)&C[(size_t)(row + 8) * N + col] = v1;
        }
    }
}

// =====================================================================
// Persistent GRU layer kernel — warp-specialized.
// grid = NCTA (128), 256 threads. CTA b owns hidden cols [b*8, b*8+8).
// Weight slice (24 x 1024) smem-resident as tf32.
// Warps 0-3: consumers — each owns one 16-row M-tile with FULL K
//            accumulation (no k-split, no reduction phase).
// Warps 4-7: producers — issue all cp.asyncs for the h stream
//            (3-slot ring of k=128 chunks) and the wait_groups.
// Step sync: one release-atomic per CTA; threads 0-7 acquire-poll the
// 8 chunk counters in parallel at step start.
// =====================================================================
#define WSTRIDE 1032
#define ACH     136      // A chunk row stride (128 + 8)

__global__ __launch_bounds__(256, 1)
void gru_layer(const float* __restrict__ w_hh, const float* __restrict__ b_hh)
{
    extern __shared__ char smraw[];
    unsigned* Bs  = (unsigned*)smraw;                         // [24][WSTRIDE]
    float*    As  = (float*)(smraw + 24 * WSTRIDE * 4);       // [3][64][ACH]

    const int tid   = threadIdx.x;
    const int lane  = tid & 31;
    const int warp  = tid >> 5;
    const int gq    = lane >> 2;
    const int t4    = lane & 3;
    const int r0    = (warp & 3) * 16;   // consumer M-tile rows
    const int j0    = blockIdx.x * JSL;
    const int jc    = j0 + 2 * t4;
    const int cj    = j0 >> 7;           // chunk containing this CTA's columns
    const bool consumer = (warp < 4);

    // ---- preload weight slice (24 x 1024) as tf32 ----
    for (int e = tid; e < 24 * 256; e += 256) {
        int row = e >> 8;
        int c4  = (e & 255) * 4;
        int gate = row >> 3, jj = row & 7;
        float4 v = *(const float4*)&w_hh[(size_t)(gate * HH + j0 + jj) * HH + c4];
        uint4 u; u.x = f2tf(v.x); u.y = f2tf(v.y); u.z = f2tf(v.z); u.w = f2tf(v.w);
        *(uint4*)&Bs[row * WSTRIDE + c4] = u;
    }
    __syncthreads();

    // ---- hoist b_hh ----
    float2 bhr = make_float2(0.f, 0.f), bhz = bhr, bhn = bhr;
    if (consumer) {
        bhr = *(const float2*)&b_hh[jc];
        bhz = *(const float2*)&b_hh[HH + jc];
        bhn = *(const float2*)&b_hh[2 * HH + jc];
    }

    for (int t = 0; t < TT; ++t) {
        const float* h_in  = g_h + (size_t)(t & 1) * (BB * HH);
        float*       h_out = g_h + (size_t)((t + 1) & 1) * (BB * HH);
        const float* xg_t  = g_xg + (size_t)t * BB * G3;
        float*       y_t   = g_y  + (size_t)t * BB * HH;

        // ---- prefetch xg operands BEFORE the barrier (always ready) ----
        float2 xr0, xz0, xn0, xr1, xz1, xn1, hold0, hold1;
        if (consumer) {
            const float* xp0 = xg_t + (size_t)(r0 + gq) * G3 + jc;
            const float* xp1 = xg_t + (size_t)(r0 + gq + 8) * G3 + jc;
            xr0 = *(const float2*)(xp0);
            xz0 = *(const float2*)(xp0 + HH);
            xn0 = *(const float2*)(xp0 + 2 * HH);
            xr1 = *(const float2*)(xp1);
            xz1 = *(const float2*)(xp1 + HH);
            xn1 = *(const float2*)(xp1 + 2 * HH);
        }

        // ---- step barrier: wait for all 8 chunk groups of step t-1 ----
        if (tid < 8) {
            const unsigned tgt = 16u * (unsigned)t;
            const unsigned* fp = &g_flag[tid * 32];
            unsigned v;
            do {
                asm volatile("ld.acquire.gpu.global.u32 %0, [%1];" : "=r"(v) : "l"(fp));
            } while (v < tgt);
        }
        __syncthreads();

        // producers issue chunks (16 float4s per producer thread per chunk)
        auto issue = [&](int slot, int c) {
            if (warp >= 4) {
                const int ptid = tid - 128;          // 0..127
#pragma unroll
                for (int i = 0; i < 16; ++i) {
                    int e = ptid + 128 * i;          // 2048 float4s per chunk
                    int row = e >> 5, c4 = (e & 31) * 4;
                    const float* src = h_in + row * HH + c * 128 + c4;
                    unsigned dst = (unsigned)__cvta_generic_to_shared(
                        &As[(slot * 64 + row) * ACH + c4]);
                    asm volatile("cp.async.cg.shared.global [%0], [%1], 16;"
                                 :: "r"(dst), "l"(src));
                }
                asm volatile("cp.async.commit_group;" ::: "memory");
            }
        };

        issue(0, 0);
        issue(1, 1);

        // h-side epilogue operands (after the barrier)
        if (consumer) {
            hold0 = *(const float2*)&h_in[(r0 + gq) * HH + jc];
            hold1 = *(const float2*)&h_in[(r0 + gq + 8) * HH + jc];
        }

        float acc[3][4];
#pragma unroll
        for (int ni = 0; ni < 3; ++ni)
#pragma unroll
            for (int r = 0; r < 4; ++r) acc[ni][r] = 0.0f;

        for (int c = 0; c < 8; ++c) {
            if (warp >= 4) {
                if (c < 7) asm volatile("cp.async.wait_group 1;" ::: "memory");
                else       asm volatile("cp.async.wait_group 0;" ::: "memory");
            }
            __syncthreads();                 // chunk c visible; slot (c+2)%3 free
            if (c + 2 < 8) issue((c + 2) % 3, c + 2);

            if (consumer) {
                const int abase = (c % 3) * 64 * ACH;
                const int cb0   = c * 128;
#pragma unroll
                for (int kk = 0; kk < 16; ++kk) {
                    const int ca = kk * 8 + 2 * t4;
                    unsigned a[4];
                    float2 x0 = *(const float2*)&As[abase + (r0 + gq) * ACH + ca];
                    float2 x1 = *(const float2*)&As[abase + (r0 + gq + 8) * ACH + ca];
                    a[0] = f2tf(x0.x); a[1] = f2tf(x1.x);
                    a[2] = f2tf(x0.y); a[3] = f2tf(x1.y);
#pragma unroll
                    for (int ni = 0; ni < 3; ++ni) {
                        uint2 bb = *(const uint2*)&Bs[(ni * 8 + gq) * WSTRIDE + cb0 + ca];
                        unsigned br[2] = { bb.x, bb.y };
                        mma8(acc[ni], a, br);
                    }
                }
            }
        }

        // ---- fused gate epilogue (consumers; accumulators are complete) ----
        if (consumer) {
            float r00 = sigmoid_fast(xr0.x + acc[0][0] + bhr.x);
            float r01 = sigmoid_fast(xr0.y + acc[0][1] + bhr.y);
            float r10 = sigmoid_fast(xr1.x + acc[0][2] + bhr.x);
            float r11 = sigmoid_fast(xr1.y + acc[0][3] + bhr.y);
            float z00 = sigmoid_fast(xz0.x + acc[1][0] + bhz.x);
            float z01 = sigmoid_fast(xz0.y + acc[1][1] + bhz.y);
            float z10 = sigmoid_fast(xz1.x + acc[1][2] + bhz.x);
            float z11 = sigmoid_fast(xz1.y + acc[1][3] + bhz.y);
            float n00 = tanh_fast(xn0.x + r00 * (acc[2][0] + bhn.x));
            float n01 = tanh_fast(xn0.y + r01 * (acc[2][1] + bhn.y));
            float n10 = tanh_fast(xn1.x + r10 * (acc[2][2] + bhn.x));
            float n11 = tanh_fast(xn1.y + r11 * (acc[2][3] + bhn.y));

            float2 o0 = make_float2((1.f - z00) * n00 + z00 * hold0.x,
                                    (1.f - z01) * n01 + z01 * hold0.y);
            float2 o1 = make_float2((1.f - z10) * n10 + z10 * hold1.x,
                                    (1.f - z11) * n11 + z11 * hold1.y);
            *(float2*)&h_out[(r0 + gq) * HH + jc]     = o0;
            *(float2*)&h_out[(r0 + gq + 8) * HH + jc] = o1;
            *(float2*)&y_t  [(r0 + gq) * HH + jc]     = o0;
            *(float2*)&y_t  [(r0 + gq + 8) * HH + jc] = o1;
        }

        // ---- publish: syncthreads gives happens-before; one release atomic ----
        __syncthreads();
        if (tid == 0) {
            asm volatile("red.release.gpu.global.add.u32 [%0], %1;"
                         :: "l"(&g_flag[cj * 32]), "r"(1u) : "memory");
        }
    }
}

// =====================================================================
// init hidden state (parity buffer 0) + reset producer flags
// =====================================================================
__global__ void copy_h(const float* __restrict__ src)
{
    int i = blockIdx.x * blockDim.x + threadIdx.x;
    if (i < BB * HH) g_h[i] = src[i];
    if (i < 8 * 32) g_flag[i] = 0;
}

// =====================================================================
// LayerNorm over last dim (1024), one block per row
// =====================================================================
__global__ __launch_bounds__(256)
void ln_kernel(const float* __restrict__ y, const float* __restrict__ gamma,
               const float* __restrict__ beta, float* __restrict__ out)
{
    __shared__ float sh[16];
    const size_t row = blockIdx.x;
    const int tid = threadIdx.x, lane = tid & 31, warp = tid >> 5;

    float4 v = ((const float4*)(y + row * HH))[tid];
    float s = v.x + v.y + v.z + v.w;
    float q = v.x * v.x + v.y * v.y + v.z * v.z + v.w * v.w;
#pragma unroll
    for (int o = 16; o > 0; o >>= 1) {
        s += __shfl_xor_sync(0xffffffffu, s, o);
        q += __shfl_xor_sync(0xffffffffu, q, o);
    }
    if (lane == 0) { sh[warp] = s; sh[8 + warp] = q; }
    __syncthreads();
    if (tid == 0) {
        float S = 0.0f, Q = 0.0f;
#pragma unroll
        for (int i = 0; i < 8; ++i) { S += sh[i]; Q += sh[8 + i]; }
        sh[0] = S; sh[8] = Q;
    }
    __syncthreads();
    const float mu   = sh[0] * (1.0f / HH);
    const float var  = sh[8] * (1.0f / HH) - mu * mu;
    const float rstd = rsqrtf(var + 1e-5f);

    float4 gm = ((const float4*)gamma)[tid];
    float4 bt = ((const float4*)beta)[tid];
    float4 o4;
    o4.x = (v.x - mu) * rstd * gm.x + bt.x;
    o4.y = (v.y - mu) * rstd * gm.y + bt.y;
    o4.z = (v.z - mu) * rstd * gm.z + bt.z;
    o4.w = (v.w - mu) * rstd * gm.w + bt.w;
    ((float4*)(out + row * HH))[tid] = o4;
}

// =====================================================================
// launcher  (8 graph nodes total)
// =====================================================================
extern "C" void kernel_launch(void* const* d_in, const int* in_sizes, int n_in,
                              void* d_out, int out_size)
{
    const float* x      = (const float*)d_in[0];
    const float* h      = (const float*)d_in[1];
    const float* w_ih0  = (const float*)d_in[2];
    const float* w_hh0  = (const float*)d_in[3];
    const float* b_ih0  = (const float*)d_in[4];
    const float* b_hh0  = (const float*)d_in[5];
    const float* w_ih1  = (const float*)d_in[6];
    const float* w_hh1  = (const float*)d_in[7];
    const float* b_ih1  = (const float*)d_in[8];
    const float* b_hh1  = (const float*)d_in[9];
    const float* ln_g   = (const float*)d_in[10];
    const float* ln_b   = (const float*)d_in[11];
    const float* ff_w   = (const float*)d_in[12];
    const float* ff_b   = (const float*)d_in[13];
    float* out = (float*)d_out;

    float* xg = nullptr;
    float* y  = nullptr;
    cudaGetSymbolAddress((void**)&xg, g_xg);
    cudaGetSymbolAddress((void**)&y,  g_y);

    const int smem_gru = 24 * WSTRIDE * 4 + 3 * 64 * ACH * 4;
    cudaFuncSetAttribute(gru_layer, cudaFuncAttributeMaxDynamicSharedMemorySize, smem_gru);

    // layer 0: input-side gate projections for all timesteps
    gemm_tn<<<dim3(G3 / 128, TBR / 128), 256>>>(x, w_ih0, b_ih0, xg, TBR, G3, DIN);

    // layer 0 recurrence (persistent)
    copy_h<<<(BB * HH + 255) / 256, 256>>>(h);
    gru_layer<<<NCTA, 256, smem_gru>>>(w_hh0, b_hh0);

    // layer 1: input-side gate projections
    gemm_tn<<<dim3(G3 / 128, TBR / 128), 256>>>(y, w_ih1, b_ih1, xg, TBR, G3, HH);

    // layer 1 recurrence (persistent)
    copy_h<<<(BB * HH + 255) / 256, 256>>>(h + BB * HH);
    gru_layer<<<NCTA, 256, smem_gru>>>(w_hh1, b_hh1);

    // LayerNorm (output reuses g_xg buffer)
    ln_kernel<<<TBR, 256>>>(y, ln_g, ln_b, xg);

    // output projection
    gemm_tn<<<dim3(DOUT / 128, TBR / 128), 256>>>(xg, ff_w, ff_b, out, TBR, DOUT, HH);
}